// round 2
// baseline (speedup 1.0000x reference)
#include <cuda_runtime.h>

// ---------------- problem constants ----------------
#define NPTS 32768          // B*S = 8*4096
#define DD   512            // feature dim
#define KC   4096           // codes per codebook
#define LC   3              // layers
#define NQ   ((size_t)NPTS * DD)        // 16777216 quantized_sum elements
#define NIDX ((size_t)NPTS * LC)        // 98304 index elements

// ---------------- device scratch (static; no allocation) ----------------
__device__ float g_resid[NPTS * DD];            // 64 MB residual buffer
__device__ float g_c[LC * KC];                  // 0.5*||E_k||^2
__device__ unsigned long long g_best[NPTS];     // packed (score, ~col)
__device__ int g_counts[LC * KC];               // histogram per layer
__device__ double g_commit;                     // sum of residual^2 across layers
__device__ float g_perp[LC];                    // per-layer perplexity

// ---------------- init / zero kernels ----------------
__global__ void init_kernel() {
    int i = blockIdx.x * blockDim.x + threadIdx.x;
    if (i < NPTS) g_best[i] = 0ULL;
    if (i < LC * KC) g_counts[i] = 0;
    if (i == 0) g_commit = 0.0;
}

__global__ void zero_best_kernel() {
    int i = blockIdx.x * blockDim.x + threadIdx.x;
    if (i < NPTS) g_best[i] = 0ULL;
}

// ---------------- 0.5*||E||^2 per codebook row ----------------
__global__ void colnorm_kernel(const float* __restrict__ cb) {
    int warp = (blockIdx.x * blockDim.x + threadIdx.x) >> 5;
    int lane = threadIdx.x & 31;
    if (warp >= LC * KC) return;
    const float4* row = (const float4*)(cb + (size_t)warp * DD);
    float s = 0.f;
    #pragma unroll
    for (int i = lane; i < DD / 4; i += 32) {
        float4 v = row[i];
        s += v.x * v.x + v.y * v.y + v.z * v.z + v.w * v.w;
    }
    #pragma unroll
    for (int o = 16; o; o >>= 1) s += __shfl_down_sync(0xffffffffu, s, o);
    if (lane == 0) g_c[warp] = 0.5f * s;
}

// ---------------- fused GEMM (scores) + row argmax ----------------
// score[n][k] = resid[n] . E[k] - 0.5*||E[k]||^2 ; best per n via packed atomicMax.
// 128x128 tile, BK=16, 256 threads, 8x8 microtile.
__global__ __launch_bounds__(256) void gemm_argmax_kernel(
    const float* __restrict__ Ain, const float* __restrict__ cb,
    int layer, int use_resid)
{
    const float* A = use_resid ? g_resid : Ain;
    const float* E = cb + (size_t)layer * KC * DD;
    const float* c = g_c + layer * KC;

    __shared__ __align__(16) float As[16][132];
    __shared__ __align__(16) float Bs[16][132];

    int tid = threadIdx.x;
    int tx = tid & 15, ty = tid >> 4;
    int m0 = blockIdx.x * 128, n0 = blockIdx.y * 128;

    float acc[8][8] = {};

    for (int k0 = 0; k0 < DD; k0 += 16) {
        #pragma unroll
        for (int i = 0; i < 2; i++) {
            int f = tid + i * 256;          // 0..511
            int m = f >> 2;                 // 0..127
            int kq = (f & 3) << 2;          // 0,4,8,12
            float4 va = *(const float4*)(A + (size_t)(m0 + m) * DD + k0 + kq);
            As[kq + 0][m] = va.x; As[kq + 1][m] = va.y;
            As[kq + 2][m] = va.z; As[kq + 3][m] = va.w;
            float4 vb = *(const float4*)(E + (size_t)(n0 + m) * DD + k0 + kq);
            Bs[kq + 0][m] = vb.x; Bs[kq + 1][m] = vb.y;
            Bs[kq + 2][m] = vb.z; Bs[kq + 3][m] = vb.w;
        }
        __syncthreads();
        #pragma unroll
        for (int k = 0; k < 16; k++) {
            float a[8], b[8];
            *(float4*)&a[0] = *(const float4*)&As[k][ty * 8];
            *(float4*)&a[4] = *(const float4*)&As[k][ty * 8 + 4];
            *(float4*)&b[0] = *(const float4*)&Bs[k][tx * 8];
            *(float4*)&b[4] = *(const float4*)&Bs[k][tx * 8 + 4];
            #pragma unroll
            for (int i = 0; i < 8; i++)
                #pragma unroll
                for (int j = 0; j < 8; j++)
                    acc[i][j] = fmaf(a[i], b[j], acc[i][j]);
        }
        __syncthreads();
    }

    // epilogue: per-row argmax over this 128-col tile, then global atomicMax
    #pragma unroll
    for (int i = 0; i < 8; i++) {
        unsigned long long bp = 0ULL;
        #pragma unroll
        for (int j = 0; j < 8; j++) {
            int col = n0 + tx * 8 + j;
            float s = acc[i][j] - __ldg(&c[col]);
            unsigned u = __float_as_uint(s);
            u = (u & 0x80000000u) ? ~u : (u | 0x80000000u);  // order-preserving map
            unsigned long long p = ((unsigned long long)u << 32)
                                 | (unsigned long long)(0xFFFFFFFFu - (unsigned)col);
            bp = p > bp ? p : bp;
        }
        #pragma unroll
        for (int o = 8; o; o >>= 1) {
            unsigned long long q = __shfl_down_sync(0xffffffffu, bp, o, 16);
            bp = q > bp ? q : bp;
        }
        if (tx == 0) atomicMax(&g_best[m0 + ty * 8 + i], bp);
    }
}

// ---------------- gather + residual update + commit + histogram ----------------
template <bool LAST>
__global__ void assign_kernel(const float* __restrict__ cbL, const float* __restrict__ z,
                              float* __restrict__ out_q, float* __restrict__ out_idx,
                              int layer, int first)
{
    int n = blockIdx.x;
    int t = threadIdx.x;  // 128 threads, one float4 each (D=512)
    unsigned long long p = g_best[n];
    int idx = (int)(0xFFFFFFFFu - (unsigned)(p & 0xFFFFFFFFull));
    if (t == 0) {
        out_idx[(size_t)n * LC + layer] = (float)idx;
        atomicAdd(&g_counts[layer * KC + idx], 1);
    }
    const float4* e = (const float4*)(cbL + (size_t)idx * DD);
    const float4* rin = first ? (const float4*)(z + (size_t)n * DD)
                              : (const float4*)(g_resid + (size_t)n * DD);
    float4 rv = rin[t];
    float4 ev = e[t];
    float4 rn = make_float4(rv.x - ev.x, rv.y - ev.y, rv.z - ev.z, rv.w - ev.w);
    float s = rn.x * rn.x + rn.y * rn.y + rn.z * rn.z + rn.w * rn.w;
    if (LAST) {
        float4 zv = ((const float4*)(z + (size_t)n * DD))[t];
        ((float4*)(out_q + (size_t)n * DD))[t] =
            make_float4(zv.x - rn.x, zv.y - rn.y, zv.z - rn.z, zv.w - rn.w);
    } else {
        ((float4*)(g_resid + (size_t)n * DD))[t] = rn;
    }
    #pragma unroll
    for (int o = 16; o; o >>= 1) s += __shfl_down_sync(0xffffffffu, s, o);
    __shared__ float red[4];
    if ((t & 31) == 0) red[t >> 5] = s;
    __syncthreads();
    if (t == 0) atomicAdd(&g_commit, (double)(red[0] + red[1] + red[2] + red[3]));
}

// ---------------- perplexity + scalar finalize ----------------
__global__ void perp_kernel() {
    int l = blockIdx.x;
    int t = threadIdx.x;
    float local = 0.f;
    for (int k = t; k < KC; k += 256) {
        float p = (float)g_counts[l * KC + k] * (1.0f / (float)NPTS);
        local += p * logf(p + 1e-10f);
    }
    #pragma unroll
    for (int o = 16; o; o >>= 1) local += __shfl_down_sync(0xffffffffu, local, o);
    __shared__ float red[8];
    if ((t & 31) == 0) red[t >> 5] = local;
    __syncthreads();
    if (t == 0) {
        float s = 0.f;
        #pragma unroll
        for (int i = 0; i < 8; i++) s += red[i];
        g_perp[l] = expf(-s);
    }
}

__global__ void final_kernel(float* __restrict__ out_sc) {
    out_sc[0] = (float)(g_commit * (0.25 / (double)NQ));             // total_commit
    out_sc[1] = (g_perp[0] + g_perp[1] + g_perp[2]) * (1.0f / 3.0f); // avg_perplexity
}

// ---------------- launch ----------------
extern "C" void kernel_launch(void* const* d_in, const int* in_sizes, int n_in,
                              void* d_out, int out_size)
{
    const float* z  = (const float*)d_in[0];   // [8,4096,512] f32
    const float* cb = (const float*)d_in[1];   // [3,4096,512] f32
    float* out = (float*)d_out;
    float* out_q   = out;                      // 16777216 f32
    float* out_idx = out + NQ;                 // 98304 f32 (indices cast)
    float* out_sc  = out_idx + NIDX;           // commit, avg_perplexity

    init_kernel<<<160, 256>>>();
    colnorm_kernel<<<(LC * KC * 32 + 255) / 256, 256>>>(cb);

    dim3 gg(NPTS / 128, KC / 128);
    for (int l = 0; l < LC; l++) {
        if (l) zero_best_kernel<<<128, 256>>>();
        gemm_argmax_kernel<<<gg, 256>>>(z, cb, l, l > 0 ? 1 : 0);
        const float* cbL = cb + (size_t)l * KC * DD;
        if (l < LC - 1)
            assign_kernel<false><<<NPTS, 128>>>(cbL, z, out_q, out_idx, l, l == 0 ? 1 : 0);
        else
            assign_kernel<true><<<NPTS, 128>>>(cbL, z, out_q, out_idx, l, 0);
    }
    perp_kernel<<<LC, 256>>>();
    final_kernel<<<1, 1>>>(out_sc);
}

// round 4
// speedup vs baseline: 1.4793x; 1.4793x over previous
#include <cuda_runtime.h>
#include <cuda_bf16.h>
#include <cstdint>

#define NPTS 32768
#define DD   512
#define KC   4096
#define LC   3
#define NQ   ((size_t)NPTS * DD)
#define NIDX ((size_t)NPTS * LC)

#define MT 128
#define NTT 128
#define KT 32
#define STAGES 4
#define NKCH (DD / KT)          // 16
#define NTILES (KC / NTT)       // 32
#define MARGIN 3.0f

// smem: stages 4*(8KB A + 8KB B) = 64KB (reused as 128x128 f32 scores) + 512B cnorm
#define SMEM_STAGE 16384
#define OFF_CS 65536
#define SMEM_TOTAL 66048

__device__ float          g_resid[NPTS * DD];
__device__ __nv_bfloat16  g_ahi[NPTS * DD];
__device__ __nv_bfloat16  g_bhi[LC * KC * DD];
__device__ float          g_c[LC * KC];
__device__ float          g_s1[NPTS * NTILES];
__device__ int            g_i1[NPTS * NTILES];
__device__ float          g_s2[NPTS * NTILES];
__device__ int            g_i2[NPTS * NTILES];
__device__ float          g_s3[NPTS * NTILES];
__device__ int            g_idx[NPTS];
__device__ int            g_counts[LC * KC];
__device__ double         g_commit;
__device__ float          g_perp[LC];

__device__ __forceinline__ uint32_t smem_u32(const void* p) {
    uint32_t a;
    asm("{ .reg .u64 t; cvta.to.shared.u64 t, %1; cvt.u32.u64 %0, t; }" : "=r"(a) : "l"(p));
    return a;
}
#define CP_ASYNC16(dst, src) asm volatile("cp.async.cg.shared.global [%0], [%1], 16;" :: "r"(dst), "l"(src))
#define CP_COMMIT() asm volatile("cp.async.commit_group;" ::: "memory")
#define CP_WAIT2()  asm volatile("cp.async.wait_group 2;" ::: "memory")

__device__ __forceinline__ void ldmat4(uint32_t* r, uint32_t addr) {
    asm volatile("ldmatrix.sync.aligned.m8n8.x4.shared.b16 {%0,%1,%2,%3}, [%4];"
        : "=r"(r[0]), "=r"(r[1]), "=r"(r[2]), "=r"(r[3]) : "r"(addr));
}
__device__ __forceinline__ void mma_bf16(float* d, const uint32_t* a, const uint32_t* b) {
    asm volatile("mma.sync.aligned.m16n8k16.row.col.f32.bf16.bf16.f32 "
        "{%0,%1,%2,%3}, {%4,%5,%6,%7}, {%8,%9}, {%0,%1,%2,%3};"
        : "+f"(d[0]), "+f"(d[1]), "+f"(d[2]), "+f"(d[3])
        : "r"(a[0]), "r"(a[1]), "r"(a[2]), "r"(a[3]), "r"(b[0]), "r"(b[1]));
}
// 16B-unit swizzled offset within an 8KB (128 rows x 4 vecs) tile
__device__ __forceinline__ uint32_t swz(int r, int v) {
    return (uint32_t)((r * 4 + (v ^ ((r >> 1) & 3))) * 16);
}

__global__ void init_kernel() {
    int i = blockIdx.x * blockDim.x + threadIdx.x;
    if (i < LC * KC) g_counts[i] = 0;
    if (i == 0) g_commit = 0.0;
}
__global__ void cvt_z_kernel(const float* __restrict__ z) {
    size_t i = ((size_t)blockIdx.x * blockDim.x + threadIdx.x) * 4;
    if (i >= NQ) return;
    float4 v = *(const float4*)(z + i);
    ((__nv_bfloat162*)(g_ahi + i))[0] = __floats2bfloat162_rn(v.x, v.y);
    ((__nv_bfloat162*)(g_ahi + i))[1] = __floats2bfloat162_rn(v.z, v.w);
}
__global__ void cvt_cb_kernel(const float* __restrict__ cb) {
    size_t i = ((size_t)blockIdx.x * blockDim.x + threadIdx.x) * 4;
    if (i >= (size_t)LC * KC * DD) return;
    float4 v = *(const float4*)(cb + i);
    ((__nv_bfloat162*)(g_bhi + i))[0] = __floats2bfloat162_rn(v.x, v.y);
    ((__nv_bfloat162*)(g_bhi + i))[1] = __floats2bfloat162_rn(v.z, v.w);
}
__global__ void colnorm_kernel(const float* __restrict__ cb) {
    int warp = (blockIdx.x * blockDim.x + threadIdx.x) >> 5;
    int lane = threadIdx.x & 31;
    if (warp >= LC * KC) return;
    const float4* row = (const float4*)(cb + (size_t)warp * DD);
    float s = 0.f;
    #pragma unroll
    for (int i = lane; i < DD / 4; i += 32) {
        float4 v = row[i];
        s += v.x * v.x + v.y * v.y + v.z * v.z + v.w * v.w;
    }
    #pragma unroll
    for (int o = 16; o; o >>= 1) s += __shfl_down_sync(0xffffffffu, s, o);
    if (lane == 0) g_c[warp] = 0.5f * s;
}

// ---- coarse bf16 mma.sync GEMM + per-tile top-3 epilogue ----
__global__ __launch_bounds__(256, 2) void gemm_kernel(int layer) {
    extern __shared__ char smem[];
    uint32_t sb = smem_u32(smem);
    int tid = threadIdx.x, wid = tid >> 5, lane = tid & 31;
    int warp_m = wid >> 2, warp_n = wid & 3;
    int m0 = blockIdx.x * MT, n0 = blockIdx.y * NTT;
    const __nv_bfloat16* __restrict__ A = g_ahi;
    const __nv_bfloat16* __restrict__ B = g_bhi + (size_t)layer * KC * DD;
    const float* __restrict__ cl = g_c + layer * KC;
    float* cs = (float*)(smem + OFF_CS);
    if (tid < NTT) cs[tid] = cl[n0 + tid];

    // cp.async loader: 512 A-units + 512 B-units per stage, 256 threads x 2 each
    auto load_stage = [&](int s, int kc) {
        uint32_t aBase = sb + s * SMEM_STAGE;
        uint32_t bBase = aBase + 8192;
        #pragma unroll
        for (int i = 0; i < 2; i++) {
            int f = tid + i * 256;          // 0..511
            int r = f >> 2, v = f & 3;
            const __nv_bfloat16* srcA = A + (size_t)(m0 + r) * DD + kc * KT + v * 8;
            CP_ASYNC16(aBase + swz(r, v), srcA);
            const __nv_bfloat16* srcB = B + (size_t)(n0 + r) * DD + kc * KT + v * 8;
            CP_ASYNC16(bBase + swz(r, v), srcB);
        }
    };

    float acc[4][4][4];
    #pragma unroll
    for (int mi = 0; mi < 4; mi++)
        #pragma unroll
        for (int ni = 0; ni < 4; ni++)
            #pragma unroll
            for (int e = 0; e < 4; e++) acc[mi][ni][e] = 0.f;

    #pragma unroll
    for (int s = 0; s < STAGES - 1; s++) { load_stage(s, s); CP_COMMIT(); }

    for (int kc = 0; kc < NKCH; kc++) {
        CP_WAIT2();
        __syncthreads();
        int st = kc & (STAGES - 1);
        uint32_t aBase = sb + st * SMEM_STAGE;
        uint32_t bBase = aBase + 8192;
        #pragma unroll
        for (int kk = 0; kk < 2; kk++) {
            uint32_t af[4][4], bf[2][4];
            #pragma unroll
            for (int mi = 0; mi < 4; mi++) {
                int r = warp_m * 64 + mi * 16 + (lane & 15);
                int v = 2 * kk + (lane >> 4);
                ldmat4(af[mi], aBase + swz(r, v));
            }
            #pragma unroll
            for (int nh = 0; nh < 2; nh++) {
                int r = warp_n * 32 + nh * 16 + (lane & 7) + ((lane >> 4) << 3);
                int v = 2 * kk + ((lane >> 3) & 1);
                ldmat4(bf[nh], bBase + swz(r, v));
            }
            #pragma unroll
            for (int mi = 0; mi < 4; mi++) {
                mma_bf16(acc[mi][0], af[mi], &bf[0][0]);
                mma_bf16(acc[mi][1], af[mi], &bf[0][2]);
                mma_bf16(acc[mi][2], af[mi], &bf[1][0]);
                mma_bf16(acc[mi][3], af[mi], &bf[1][2]);
            }
        }
        __syncthreads();
        if (kc + STAGES - 1 < NKCH) load_stage((kc + STAGES - 1) & (STAGES - 1), kc + STAGES - 1);
        CP_COMMIT();
    }

    // dump accumulators to smem scores [128][128]
    float* scores = (float*)smem;
    int r0 = warp_m * 64 + (lane >> 2);
    int c0 = warp_n * 32 + (lane & 3) * 2;
    #pragma unroll
    for (int mi = 0; mi < 4; mi++)
        #pragma unroll
        for (int ni = 0; ni < 4; ni++) {
            int r = r0 + mi * 16, c = c0 + ni * 8;
            scores[r * NTT + c]             = acc[mi][ni][0];
            scores[r * NTT + c + 1]         = acc[mi][ni][1];
            scores[(r + 8) * NTT + c]       = acc[mi][ni][2];
            scores[(r + 8) * NTT + c + 1]   = acc[mi][ni][3];
        }
    __syncthreads();

    if (tid < 128) {
        int r = tid;
        float s1 = -3.0e38f, s2 = -3.0e38f, s3 = -3.0e38f;
        int i1 = 0, i2 = 0;
        #pragma unroll 8
        for (int j = 0; j < 32; j++) {
            int q = (j + r) & 31;                       // rotated, conflict-free
            float4 v = *(float4*)&scores[r * NTT + q * 4];
            #pragma unroll
            for (int e = 0; e < 4; e++) {
                float sc = (&v.x)[e] - cs[q * 4 + e];
                int col = n0 + q * 4 + e;
                if (sc > s1)      { s3 = s2; s2 = s1; i2 = i1; s1 = sc; i1 = col; }
                else if (sc > s2) { s3 = s2; s2 = sc; i2 = col; }
                else if (sc > s3) { s3 = sc; }
            }
        }
        int row = m0 + r, t = blockIdx.y;
        g_s1[row * NTILES + t] = s1;  g_i1[row * NTILES + t] = i1;
        g_s2[row * NTILES + t] = s2;  g_i2[row * NTILES + t] = i2;
        g_s3[row * NTILES + t] = s3;
    }
}

// ---- exact fp32 re-rank (warp per row) ----
__global__ __launch_bounds__(128) void rerank_kernel(const float* __restrict__ z,
                                                     const float* __restrict__ cb, int layer) {
    int warp = (blockIdx.x * blockDim.x + threadIdx.x) >> 5;
    int lane = threadIdx.x & 31;
    if (warp >= NPTS) return;
    int row = warp;
    const float* Ar = (layer == 0) ? z + (size_t)row * DD : g_resid + (size_t)row * DD;
    const float* El = cb + (size_t)layer * KC * DD;
    const float* cl = g_c + layer * KC;

    float ts1 = g_s1[row * NTILES + lane];
    int   ti1 = g_i1[row * NTILES + lane];
    float ts2 = g_s2[row * NTILES + lane];
    int   ti2 = g_i2[row * NTILES + lane];
    float ts3 = g_s3[row * NTILES + lane];

    float best = ts1;
    #pragma unroll
    for (int o = 16; o; o >>= 1) best = fmaxf(best, __shfl_xor_sync(0xffffffffu, best, o));
    float thr = best - MARGIN;
    bool slow = __any_sync(0xffffffffu, ts3 >= thr);

    float a[16];
    #pragma unroll
    for (int j = 0; j < 4; j++) {
        float4 v = ((const float4*)Ar)[j * 32 + lane];
        a[j * 4 + 0] = v.x; a[j * 4 + 1] = v.y; a[j * 4 + 2] = v.z; a[j * 4 + 3] = v.w;
    }
    float bs = -3.0e38f; int bi = 0x7fffffff;
    auto eval = [&](int k) {
        const float4* E4 = (const float4*)(El + (size_t)k * DD);
        float s = 0.f;
        #pragma unroll
        for (int j = 0; j < 4; j++) {
            float4 e = E4[j * 32 + lane];
            s = fmaf(a[j * 4 + 0], e.x, s); s = fmaf(a[j * 4 + 1], e.y, s);
            s = fmaf(a[j * 4 + 2], e.z, s); s = fmaf(a[j * 4 + 3], e.w, s);
        }
        #pragma unroll
        for (int o = 16; o; o >>= 1) s += __shfl_xor_sync(0xffffffffu, s, o);
        s -= cl[k];
        if (s > bs || (s == bs && k < bi)) { bs = s; bi = k; }
    };
    if (!slow) {
        for (int t = 0; t < NTILES; t++) {
            float v1 = __shfl_sync(0xffffffffu, ts1, t);
            float v2 = __shfl_sync(0xffffffffu, ts2, t);
            int k1 = __shfl_sync(0xffffffffu, ti1, t);
            int k2 = __shfl_sync(0xffffffffu, ti2, t);
            if (v1 >= thr) eval(k1);
            if (v2 >= thr) eval(k2);
        }
    } else {
        for (int k = 0; k < KC; k++) eval(k);
    }
    if (lane == 0) g_idx[row] = bi;
}

// ---- gather + residual + commit + histogram (+ bf16 residual for next layer) ----
template <bool LAST>
__global__ void assign_kernel(const float* __restrict__ cbL, const float* __restrict__ z,
                              float* __restrict__ out_q, float* __restrict__ out_idx,
                              int layer, int first) {
    int n = blockIdx.x;
    int t = threadIdx.x;  // 128 threads
    int idx = g_idx[n];
    if (t == 0) {
        out_idx[(size_t)n * LC + layer] = (float)idx;
        atomicAdd(&g_counts[layer * KC + idx], 1);
    }
    float4 ev = ((const float4*)(cbL + (size_t)idx * DD))[t];
    float4 rv = first ? ((const float4*)(z + (size_t)n * DD))[t]
                      : ((const float4*)(g_resid + (size_t)n * DD))[t];
    float4 rn = make_float4(rv.x - ev.x, rv.y - ev.y, rv.z - ev.z, rv.w - ev.w);
    float s = rn.x * rn.x + rn.y * rn.y + rn.z * rn.z + rn.w * rn.w;
    if (LAST) {
        float4 zv = ((const float4*)(z + (size_t)n * DD))[t];
        ((float4*)(out_q + (size_t)n * DD))[t] =
            make_float4(zv.x - rn.x, zv.y - rn.y, zv.z - rn.z, zv.w - rn.w);
    } else {
        ((float4*)(g_resid + (size_t)n * DD))[t] = rn;
        __nv_bfloat162* bh = (__nv_bfloat162*)(g_ahi + (size_t)n * DD + t * 4);
        bh[0] = __floats2bfloat162_rn(rn.x, rn.y);
        bh[1] = __floats2bfloat162_rn(rn.z, rn.w);
    }
    #pragma unroll
    for (int o = 16; o; o >>= 1) s += __shfl_down_sync(0xffffffffu, s, o);
    __shared__ float red[4];
    if ((t & 31) == 0) red[t >> 5] = s;
    __syncthreads();
    if (t == 0) atomicAdd(&g_commit, (double)(red[0] + red[1] + red[2] + red[3]));
}

__global__ void perp_kernel() {
    int l = blockIdx.x, t = threadIdx.x;
    float local = 0.f;
    for (int k = t; k < KC; k += 256) {
        float p = (float)g_counts[l * KC + k] * (1.0f / (float)NPTS);
        local += p * logf(p + 1e-10f);
    }
    #pragma unroll
    for (int o = 16; o; o >>= 1) local += __shfl_down_sync(0xffffffffu, local, o);
    __shared__ float red[8];
    if ((t & 31) == 0) red[t >> 5] = local;
    __syncthreads();
    if (t == 0) {
        float s = 0.f;
        #pragma unroll
        for (int i = 0; i < 8; i++) s += red[i];
        g_perp[l] = expf(-s);
    }
}
__global__ void final_kernel(float* __restrict__ out_sc) {
    out_sc[0] = (float)(g_commit * (0.25 / (double)NQ));
    out_sc[1] = (g_perp[0] + g_perp[1] + g_perp[2]) * (1.0f / 3.0f);
}

extern "C" void kernel_launch(void* const* d_in, const int* in_sizes, int n_in,
                              void* d_out, int out_size)
{
    const float* z  = (const float*)d_in[0];
    const float* cb = (const float*)d_in[1];
    float* out = (float*)d_out;
    float* out_q   = out;
    float* out_idx = out + NQ;
    float* out_sc  = out_idx + NIDX;

    cudaFuncSetAttribute(gemm_kernel, cudaFuncAttributeMaxDynamicSharedMemorySize, SMEM_TOTAL);

    init_kernel<<<48, 256>>>();
    cvt_z_kernel<<<(int)(NQ / 4 / 256), 256>>>(z);
    cvt_cb_kernel<<<(int)((size_t)LC * KC * DD / 4 / 256), 256>>>(cb);
    colnorm_kernel<<<(LC * KC * 32 + 255) / 256, 256>>>(cb);

    dim3 gg(NPTS / MT, KC / NTT);
    for (int l = 0; l < LC; l++) {
        gemm_kernel<<<gg, 256, SMEM_TOTAL>>>(l);
        rerank_kernel<<<NPTS / 4, 128>>>(z, cb, l);
        const float* cbL = cb + (size_t)l * KC * DD;
        if (l < LC - 1)
            assign_kernel<false><<<NPTS, 128>>>(cbL, z, out_q, out_idx, l, l == 0 ? 1 : 0);
        else
            assign_kernel<true><<<NPTS, 128>>>(cbL, z, out_q, out_idx, l, 0);
    }
    perp_kernel<<<LC, 256>>>();
    final_kernel<<<1, 1>>>(out_sc);
}

// round 5
// speedup vs baseline: 3.9675x; 2.6820x over previous
#include <cuda_runtime.h>
#include <cuda_bf16.h>
#include <cstdint>

#define NPTS 32768
#define DD   512
#define KC   4096
#define LC   3
#define NQ   ((size_t)NPTS * DD)
#define NIDX ((size_t)NPTS * LC)

#define MT 128
#define NTT 128
#define KT 32
#define STAGES 4
#define NKCH (DD / KT)          // 16
#define NTILES (KC / NTT)       // 32
#define MARGIN 2.0f

#define SMEM_STAGE 16384
#define OFF_CS 65536
#define SMEM_TOTAL 66048

__device__ float          g_resid[NPTS * DD];
__device__ __nv_bfloat16  g_ahi[NPTS * DD];
__device__ __nv_bfloat16  g_bhi[LC * KC * DD];
__device__ float          g_c[LC * KC];
__device__ float4         g_ts[NPTS * NTILES];   // per-tile top-4 scores
__device__ int4           g_ti[NPTS * NTILES];   // per-tile top-4 indices
__device__ float          g_s5[NPTS * NTILES];   // per-tile 5th-best score
__device__ int            g_counts[LC * KC];
__device__ double         g_commit;
__device__ float          g_perp[LC];

__device__ __forceinline__ uint32_t smem_u32(const void* p) {
    uint32_t a;
    asm("{ .reg .u64 t; cvta.to.shared.u64 t, %1; cvt.u32.u64 %0, t; }" : "=r"(a) : "l"(p));
    return a;
}
#define CP_ASYNC16(dst, src) asm volatile("cp.async.cg.shared.global [%0], [%1], 16;" :: "r"(dst), "l"(src))
#define CP_COMMIT() asm volatile("cp.async.commit_group;" ::: "memory")
#define CP_WAIT2()  asm volatile("cp.async.wait_group 2;" ::: "memory")

__device__ __forceinline__ void ldmat4(uint32_t* r, uint32_t addr) {
    asm volatile("ldmatrix.sync.aligned.m8n8.x4.shared.b16 {%0,%1,%2,%3}, [%4];"
        : "=r"(r[0]), "=r"(r[1]), "=r"(r[2]), "=r"(r[3]) : "r"(addr));
}
__device__ __forceinline__ void mma_bf16(float* d, const uint32_t* a, const uint32_t* b) {
    asm volatile("mma.sync.aligned.m16n8k16.row.col.f32.bf16.bf16.f32 "
        "{%0,%1,%2,%3}, {%4,%5,%6,%7}, {%8,%9}, {%0,%1,%2,%3};"
        : "+f"(d[0]), "+f"(d[1]), "+f"(d[2]), "+f"(d[3])
        : "r"(a[0]), "r"(a[1]), "r"(a[2]), "r"(a[3]), "r"(b[0]), "r"(b[1]));
}
__device__ __forceinline__ uint32_t swz(int r, int v) {
    return (uint32_t)((r * 4 + (v ^ ((r >> 1) & 3))) * 16);
}

__global__ void init_kernel() {
    int i = blockIdx.x * blockDim.x + threadIdx.x;
    if (i < LC * KC) g_counts[i] = 0;
    if (i == 0) g_commit = 0.0;
}
__global__ void cvt_z_kernel(const float* __restrict__ z) {
    size_t i = ((size_t)blockIdx.x * blockDim.x + threadIdx.x) * 4;
    if (i >= NQ) return;
    float4 v = *(const float4*)(z + i);
    ((__nv_bfloat162*)(g_ahi + i))[0] = __floats2bfloat162_rn(v.x, v.y);
    ((__nv_bfloat162*)(g_ahi + i))[1] = __floats2bfloat162_rn(v.z, v.w);
}
__global__ void cvt_cb_kernel(const float* __restrict__ cb) {
    size_t i = ((size_t)blockIdx.x * blockDim.x + threadIdx.x) * 4;
    if (i >= (size_t)LC * KC * DD) return;
    float4 v = *(const float4*)(cb + i);
    ((__nv_bfloat162*)(g_bhi + i))[0] = __floats2bfloat162_rn(v.x, v.y);
    ((__nv_bfloat162*)(g_bhi + i))[1] = __floats2bfloat162_rn(v.z, v.w);
}
__global__ void colnorm_kernel(const float* __restrict__ cb) {
    int warp = (blockIdx.x * blockDim.x + threadIdx.x) >> 5;
    int lane = threadIdx.x & 31;
    if (warp >= LC * KC) return;
    const float4* row = (const float4*)(cb + (size_t)warp * DD);
    float s = 0.f;
    #pragma unroll
    for (int i = lane; i < DD / 4; i += 32) {
        float4 v = row[i];
        s += v.x * v.x + v.y * v.y + v.z * v.z + v.w * v.w;
    }
    #pragma unroll
    for (int o = 16; o; o >>= 1) s += __shfl_down_sync(0xffffffffu, s, o);
    if (lane == 0) g_c[warp] = 0.5f * s;
}

// ---- coarse bf16 mma.sync GEMM + per-tile top-4(+s5) epilogue ----
__global__ __launch_bounds__(256, 2) void gemm_kernel(int layer) {
    extern __shared__ char smem[];
    uint32_t sb = smem_u32(smem);
    int tid = threadIdx.x, wid = tid >> 5, lane = tid & 31;
    int warp_m = wid >> 2, warp_n = wid & 3;
    int m0 = blockIdx.x * MT, n0 = blockIdx.y * NTT;
    const __nv_bfloat16* __restrict__ A = g_ahi;
    const __nv_bfloat16* __restrict__ B = g_bhi + (size_t)layer * KC * DD;
    const float* __restrict__ cl = g_c + layer * KC;
    float* cs = (float*)(smem + OFF_CS);
    if (tid < NTT) cs[tid] = cl[n0 + tid];

    auto load_stage = [&](int s, int kc) {
        uint32_t aBase = sb + s * SMEM_STAGE;
        uint32_t bBase = aBase + 8192;
        #pragma unroll
        for (int i = 0; i < 2; i++) {
            int f = tid + i * 256;
            int r = f >> 2, v = f & 3;
            const __nv_bfloat16* srcA = A + (size_t)(m0 + r) * DD + kc * KT + v * 8;
            CP_ASYNC16(aBase + swz(r, v), srcA);
            const __nv_bfloat16* srcB = B + (size_t)(n0 + r) * DD + kc * KT + v * 8;
            CP_ASYNC16(bBase + swz(r, v), srcB);
        }
    };

    float acc[4][4][4];
    #pragma unroll
    for (int mi = 0; mi < 4; mi++)
        #pragma unroll
        for (int ni = 0; ni < 4; ni++)
            #pragma unroll
            for (int e = 0; e < 4; e++) acc[mi][ni][e] = 0.f;

    #pragma unroll
    for (int s = 0; s < STAGES - 1; s++) { load_stage(s, s); CP_COMMIT(); }

    for (int kc = 0; kc < NKCH; kc++) {
        CP_WAIT2();
        __syncthreads();
        int st = kc & (STAGES - 1);
        uint32_t aBase = sb + st * SMEM_STAGE;
        uint32_t bBase = aBase + 8192;
        #pragma unroll
        for (int kk = 0; kk < 2; kk++) {
            uint32_t af[4][4], bf[2][4];
            #pragma unroll
            for (int mi = 0; mi < 4; mi++) {
                int r = warp_m * 64 + mi * 16 + (lane & 15);
                int v = 2 * kk + (lane >> 4);
                ldmat4(af[mi], aBase + swz(r, v));
            }
            #pragma unroll
            for (int nh = 0; nh < 2; nh++) {
                int r = warp_n * 32 + nh * 16 + (lane & 7) + ((lane >> 4) << 3);
                int v = 2 * kk + ((lane >> 3) & 1);
                ldmat4(bf[nh], bBase + swz(r, v));
            }
            #pragma unroll
            for (int mi = 0; mi < 4; mi++) {
                mma_bf16(acc[mi][0], af[mi], &bf[0][0]);
                mma_bf16(acc[mi][1], af[mi], &bf[0][2]);
                mma_bf16(acc[mi][2], af[mi], &bf[1][0]);
                mma_bf16(acc[mi][3], af[mi], &bf[1][2]);
            }
        }
        __syncthreads();
        if (kc + STAGES - 1 < NKCH) load_stage((kc + STAGES - 1) & (STAGES - 1), kc + STAGES - 1);
        CP_COMMIT();
    }

    float* scores = (float*)smem;
    int r0 = warp_m * 64 + (lane >> 2);
    int c0 = warp_n * 32 + (lane & 3) * 2;
    #pragma unroll
    for (int mi = 0; mi < 4; mi++)
        #pragma unroll
        for (int ni = 0; ni < 4; ni++) {
            int r = r0 + mi * 16, c = c0 + ni * 8;
            scores[r * NTT + c]             = acc[mi][ni][0];
            scores[r * NTT + c + 1]         = acc[mi][ni][1];
            scores[(r + 8) * NTT + c]       = acc[mi][ni][2];
            scores[(r + 8) * NTT + c + 1]   = acc[mi][ni][3];
        }
    __syncthreads();

    if (tid < 128) {
        int r = tid;
        float t1 = -3.0e38f, t2 = -3.0e38f, t3 = -3.0e38f, t4 = -3.0e38f, t5 = -3.0e38f;
        int j1 = 0, j2 = 0, j3 = 0, j4 = 0;
        #pragma unroll 8
        for (int j = 0; j < 32; j++) {
            int q = (j + r) & 31;
            float4 v = *(float4*)&scores[r * NTT + q * 4];
            #pragma unroll
            for (int e = 0; e < 4; e++) {
                float sc = (&v.x)[e] - cs[q * 4 + e];
                int col = n0 + q * 4 + e;
                if (sc > t1)      { t5 = t4; t4 = t3; j4 = j3; t3 = t2; j3 = j2; t2 = t1; j2 = j1; t1 = sc; j1 = col; }
                else if (sc > t2) { t5 = t4; t4 = t3; j4 = j3; t3 = t2; j3 = j2; t2 = sc; j2 = col; }
                else if (sc > t3) { t5 = t4; t4 = t3; j4 = j3; t3 = sc; j3 = col; }
                else if (sc > t4) { t5 = t4; t4 = sc; j4 = col; }
                else if (sc > t5) { t5 = sc; }
            }
        }
        int row = m0 + r, t = blockIdx.y;
        g_ts[row * NTILES + t] = make_float4(t1, t2, t3, t4);
        g_ti[row * NTILES + t] = make_int4(j1, j2, j3, j4);
        g_s5[row * NTILES + t] = t5;
    }
}

// ---- fused exact re-rank + assign (warp per row) ----
template <bool LAST>
__global__ __launch_bounds__(128) void rerank_assign_kernel(
    const float* __restrict__ z, const float* __restrict__ cb,
    float* __restrict__ out_q, float* __restrict__ out_idx, int layer)
{
    int warp = (blockIdx.x * blockDim.x + threadIdx.x) >> 5;
    int lane = threadIdx.x & 31;
    if (warp >= NPTS) return;
    int row = warp;
    const float* Ar = (layer == 0) ? z + (size_t)row * DD : g_resid + (size_t)row * DD;
    const float* El = cb + (size_t)layer * KC * DD;
    const float* cl = g_c + layer * KC;

    // tile summaries: lane == tile (NTILES == 32)
    float4 ts = g_ts[row * NTILES + lane];
    int4   ti = g_ti[row * NTILES + lane];
    float  s5 = g_s5[row * NTILES + lane];

    float best = ts.x;
    #pragma unroll
    for (int o = 16; o; o >>= 1) best = fmaxf(best, __shfl_xor_sync(0xffffffffu, best, o));
    float thr = best - MARGIN;
    bool slow = __any_sync(0xffffffffu, s5 >= thr);

    // residual row in registers (element (j*32+lane)*4 + e)
    float a[16];
    #pragma unroll
    for (int j = 0; j < 4; j++) {
        float4 v = ((const float4*)Ar)[j * 32 + lane];
        a[j * 4 + 0] = v.x; a[j * 4 + 1] = v.y; a[j * 4 + 2] = v.z; a[j * 4 + 3] = v.w;
    }

    float bs = -3.0e38f; int bi = 0x7fffffff;
    auto eval = [&](int k) {
        const float4* E4 = (const float4*)(El + (size_t)k * DD);
        float s = 0.f;
        #pragma unroll
        for (int j = 0; j < 4; j++) {
            float4 e = E4[j * 32 + lane];
            s = fmaf(a[j * 4 + 0], e.x, s); s = fmaf(a[j * 4 + 1], e.y, s);
            s = fmaf(a[j * 4 + 2], e.z, s); s = fmaf(a[j * 4 + 3], e.w, s);
        }
        #pragma unroll
        for (int o = 16; o; o >>= 1) s += __shfl_xor_sync(0xffffffffu, s, o);
        s -= cl[k];
        if (s > bs || (s == bs && k < bi)) { bs = s; bi = k; }
    };

    if (slow) {
        for (int k = 0; k < KC; k++) eval(k);
    } else {
        unsigned m0b = __ballot_sync(0xffffffffu, ts.x >= thr);
        unsigned m1b = __ballot_sync(0xffffffffu, ts.y >= thr);
        unsigned m2b = __ballot_sync(0xffffffffu, ts.z >= thr);
        unsigned m3b = __ballot_sync(0xffffffffu, ts.w >= thr);
        int cnt = __popc(m0b) + __popc(m1b) + __popc(m2b) + __popc(m3b);
        if (cnt == 1) {
            int t = __ffs(m0b) - 1;
            bi = __shfl_sync(0xffffffffu, ti.x, t);
        } else {
            unsigned m = m0b;
            while (m) { int t = __ffs(m) - 1; m &= m - 1; eval(__shfl_sync(0xffffffffu, ti.x, t)); }
            m = m1b;
            while (m) { int t = __ffs(m) - 1; m &= m - 1; eval(__shfl_sync(0xffffffffu, ti.y, t)); }
            m = m2b;
            while (m) { int t = __ffs(m) - 1; m &= m - 1; eval(__shfl_sync(0xffffffffu, ti.z, t)); }
            m = m3b;
            while (m) { int t = __ffs(m) - 1; m &= m - 1; eval(__shfl_sync(0xffffffffu, ti.w, t)); }
        }
    }

    // ---- assign: residual update with row in registers ----
    if (lane == 0) {
        out_idx[(size_t)row * LC + layer] = (float)bi;
        atomicAdd(&g_counts[layer * KC + bi], 1);
    }
    const float4* E4 = (const float4*)(El + (size_t)bi * DD);
    float csum = 0.f;
    #pragma unroll
    for (int j = 0; j < 4; j++) {
        float4 e = E4[j * 32 + lane];
        float4 rn = make_float4(a[j * 4 + 0] - e.x, a[j * 4 + 1] - e.y,
                                a[j * 4 + 2] - e.z, a[j * 4 + 3] - e.w);
        csum += rn.x * rn.x + rn.y * rn.y + rn.z * rn.z + rn.w * rn.w;
        if (LAST) {
            float4 zv = ((const float4*)(z + (size_t)row * DD))[j * 32 + lane];
            ((float4*)(out_q + (size_t)row * DD))[j * 32 + lane] =
                make_float4(zv.x - rn.x, zv.y - rn.y, zv.z - rn.z, zv.w - rn.w);
        } else {
            ((float4*)(g_resid + (size_t)row * DD))[j * 32 + lane] = rn;
            __nv_bfloat162* bh = (__nv_bfloat162*)(g_ahi + (size_t)row * DD + (j * 32 + lane) * 4);
            bh[0] = __floats2bfloat162_rn(rn.x, rn.y);
            bh[1] = __floats2bfloat162_rn(rn.z, rn.w);
        }
    }
    #pragma unroll
    for (int o = 16; o; o >>= 1) csum += __shfl_down_sync(0xffffffffu, csum, o);
    if (lane == 0) atomicAdd(&g_commit, (double)csum);
}

__global__ void perp_kernel() {
    int l = blockIdx.x, t = threadIdx.x;
    float local = 0.f;
    for (int k = t; k < KC; k += 256) {
        float p = (float)g_counts[l * KC + k] * (1.0f / (float)NPTS);
        local += p * logf(p + 1e-10f);
    }
    #pragma unroll
    for (int o = 16; o; o >>= 1) local += __shfl_down_sync(0xffffffffu, local, o);
    __shared__ float red[8];
    if ((t & 31) == 0) red[t >> 5] = local;
    __syncthreads();
    if (t == 0) {
        float s = 0.f;
        #pragma unroll
        for (int i = 0; i < 8; i++) s += red[i];
        g_perp[l] = expf(-s);
    }
}
__global__ void final_kernel(float* __restrict__ out_sc) {
    out_sc[0] = (float)(g_commit * (0.25 / (double)NQ));
    out_sc[1] = (g_perp[0] + g_perp[1] + g_perp[2]) * (1.0f / 3.0f);
}

extern "C" void kernel_launch(void* const* d_in, const int* in_sizes, int n_in,
                              void* d_out, int out_size)
{
    const float* z  = (const float*)d_in[0];
    const float* cb = (const float*)d_in[1];
    float* out = (float*)d_out;
    float* out_q   = out;
    float* out_idx = out + NQ;
    float* out_sc  = out_idx + NIDX;

    cudaFuncSetAttribute(gemm_kernel, cudaFuncAttributeMaxDynamicSharedMemorySize, SMEM_TOTAL);

    init_kernel<<<48, 256>>>();
    cvt_z_kernel<<<(int)(NQ / 4 / 256), 256>>>(z);
    cvt_cb_kernel<<<(int)((size_t)LC * KC * DD / 4 / 256), 256>>>(cb);
    colnorm_kernel<<<(LC * KC * 32 + 255) / 256, 256>>>(cb);

    dim3 gg(NPTS / MT, KC / NTT);
    for (int l = 0; l < LC; l++) {
        gemm_kernel<<<gg, 256, SMEM_TOTAL>>>(l);
        if (l < LC - 1)
            rerank_assign_kernel<false><<<NPTS / 4, 128>>>(z, cb, out_q, out_idx, l);
        else
            rerank_assign_kernel<true><<<NPTS / 4, 128>>>(z, cb, out_q, out_idx, l);
    }
    perp_kernel<<<LC, 256>>>();
    final_kernel<<<1, 1>>>(out_sc);
}